// round 16
// baseline (speedup 1.0000x reference)
#include <cuda_runtime.h>
#include <cuda_bf16.h>
#include <math.h>
#include <stdint.h>

#define BB   4
#define CIN  32
#define COUT 64
#define HH   32
#define WW   32
#define HP   34
#define WP   34
#define CF   128            // CIN*4 trig features = K per tap
#define NT   32             // M tiles: 4 b x 8 row-blocks (4 rows x 32 cols = 128 px)
#define KP2  72             // padded smem row stride in bf16 (144B)
#define HT_BYTES (128 * KP2 * 2)      // 18432 B per half-tile
#define CHUNK_BYTES (4 * HT_BYTES)    // 73728 B (Ah|Al|Bh|Bl)

#define WGT_TOTAL  (9 * COUT * CIN)       // 18432
#define FEAT_BLOCKS (BB * HP)             // 136
#define WGT_BLOCKS  (WGT_TOTAL / 256)     // 72

// ---------------- device scratch ----------------
__device__ __nv_bfloat16 g_featH[BB * HP * WP * CF];   // padded NHWC, hi
__device__ __nv_bfloat16 g_featL[BB * HP * WP * CF];   // lo
__device__ __nv_bfloat16 g_Bh[9][128 * 128];           // [tap][n][k]
__device__ __nv_bfloat16 g_Bl[9][128 * 128];
__device__ float g_part[9][NT][128][128];              // fp32 partials (18.9MB, L2-resident)

// ---------------- PTX helpers ----------------
__device__ __forceinline__ uint32_t smem_u32(const void* p) {
    uint32_t a;
    asm("{ .reg .u64 t; cvta.to.shared.u64 t, %1; cvt.u32.u64 %0, t; }" : "=r"(a) : "l"(p));
    return a;
}
#define CP_ASYNC16(dst, src) \
    asm volatile("cp.async.cg.shared.global [%0], [%1], 16;" :: "r"(dst), "l"(src))
#define CP_COMMIT() asm volatile("cp.async.commit_group;" ::: "memory")
#define CP_WAIT1()  asm volatile("cp.async.wait_group 1;" ::: "memory")
#define CP_WAIT0()  asm volatile("cp.async.wait_group 0;" ::: "memory")
#define LDSM_X4(r0, r1, r2, r3, addr) \
    asm volatile("ldmatrix.sync.aligned.m8n8.x4.shared.b16 {%0,%1,%2,%3}, [%4];" \
        : "=r"(r0), "=r"(r1), "=r"(r2), "=r"(r3) : "r"(addr))
#define MMA16816(c, a0, a1, a2, a3, b0, b1) \
    asm volatile("mma.sync.aligned.m16n8k16.row.col.f32.bf16.bf16.f32 " \
        "{%0,%1,%2,%3}, {%4,%5,%6,%7}, {%8,%9}, {%0,%1,%2,%3};" \
        : "+f"((c)[0]), "+f"((c)[1]), "+f"((c)[2]), "+f"((c)[3]) \
        : "r"(a0), "r"(a1), "r"(a2), "r"(a3), "r"(b0), "r"(b1))

__device__ __forceinline__ uint32_t pack_bf2(float a, float b) {
    __nv_bfloat162 v = __floats2bfloat162_rn(a, b);
    return *reinterpret_cast<uint32_t*>(&v);
}

// ---------------- prep ----------------
// Feature blocks (0..135): one block per (b, padded row pr). Coalesced x loads,
// smem-staged transpose, contiguous uint4 feature-row stores.
// Weight blocks (136..207): folded weight matrices.
// cos^3(x-p) = 3/4[cx*cp + sx*sp] + 1/4[c3x*c3p + s3x*s3p]
__global__ __launch_bounds__(256) void prep_kernel(const float* __restrict__ x,
                                                   const float* __restrict__ probe,
                                                   const float* __restrict__ outw) {
    const int tid = threadIdx.x;
    if (blockIdx.x < FEAT_BLOCKS) {
        __shared__ __nv_bfloat16 sH[WP * CF];   // 8704 B
        __shared__ __nv_bfloat16 sL[WP * CF];
        const int b  = blockIdx.x / HP;
        const int pr = blockIdx.x % HP;
        const bool rowin = (pr >= 1 && pr <= HH);

        for (int i = tid; i < WP * CIN; i += 256) {
            int pc = i % WP;            // consecutive tid -> consecutive pc (coalesced x)
            int c  = i / WP;
            float v = 0.0f;
            if (rowin && pc >= 1 && pc <= WW)
                v = x[((b * CIN + c) * HH + (pr - 1)) * WW + (pc - 1)];
            float s, cv;
            sincosf(v, &s, &cv);
            float f0 = cv, f1 = s;
            float f2 = cv * (4.0f * cv * cv - 3.0f);
            float f3 = s * (3.0f - 4.0f * s * s);
            float h0 = __bfloat162float(__float2bfloat16(f0));
            float h1 = __bfloat162float(__float2bfloat16(f1));
            float h2 = __bfloat162float(__float2bfloat16(f2));
            float h3 = __bfloat162float(__float2bfloat16(f3));
            int sbase = pc * CF + c * 4;
            *reinterpret_cast<uint2*>(&sH[sbase]) =
                make_uint2(pack_bf2(h0, h1), pack_bf2(h2, h3));
            *reinterpret_cast<uint2*>(&sL[sbase]) =
                make_uint2(pack_bf2(f0 - h0, f1 - h1), pack_bf2(f2 - h2, f3 - h3));
        }
        __syncthreads();

        uint4* dH = reinterpret_cast<uint4*>(&g_featH[(size_t)(b * HP + pr) * WP * CF]);
        uint4* dL = reinterpret_cast<uint4*>(&g_featL[(size_t)(b * HP + pr) * WP * CF]);
        const uint4* srcH = reinterpret_cast<const uint4*>(sH);
        const uint4* srcL = reinterpret_cast<const uint4*>(sL);
        for (int j = tid; j < WP * CF * 2 / 16; j += 256) {   // 544 chunks
            dH[j] = srcH[j];
            dL[j] = srcL[j];
        }
    } else {
        int j = (blockIdx.x - FEAT_BLOCKS) * 256 + tid;
        if (j >= WGT_TOTAL) return;
        int c  = j % CIN;
        int o  = (j / CIN) % COUT;
        int kl = j / (CIN * COUT);
        int widx = (c * COUT + o) * 9 + kl;   // (1,CIN,COUT,1,1,3,3) flat

        float sp, cp, sw, cw;
        sincosf(probe[widx], &sp, &cp);
        sincosf(outw[widx],  &sw, &cw);
        float c3p = cp * (4.0f * cp * cp - 3.0f);
        float s3p = sp * (3.0f - 4.0f * sp * sp);
        float wx[4] = {0.75f * cw * cp, 0.75f * cw * sp, 0.25f * cw * c3p, 0.25f * cw * s3p};
        float wy[4] = {0.75f * sw * cp, 0.75f * sw * sp, 0.25f * sw * c3p, 0.25f * sw * s3p};
        #pragma unroll
        for (int f = 0; f < 4; f++) {
            int col = c * 4 + f;
            float a = wx[f];
            __nv_bfloat16 hh = __float2bfloat16(a);
            g_Bh[kl][o * 128 + col] = hh;
            g_Bl[kl][o * 128 + col] = __float2bfloat16(a - __bfloat162float(hh));
            a = wy[f];
            hh = __float2bfloat16(a);
            g_Bh[kl][(o + 64) * 128 + col] = hh;
            g_Bl[kl][(o + 64) * 128 + col] = __float2bfloat16(a - __bfloat162float(hh));
        }
    }
}

// ---------------- gemm: (M-tile, tap) -> fp32 partial; 288 CTAs, 2-chunk pipe --
// 256 threads = 8 warps (2m x 4n), warp tile m64 x n32.
__global__ __launch_bounds__(256) void gemm_kernel() {
    extern __shared__ unsigned char smem[];
    const uint32_t u0 = smem_u32(smem);

    const int tid  = threadIdx.x;
    const int wid  = tid >> 5;
    const int ln   = tid & 31;
    const int tile = blockIdx.x;          // 0..31
    const int kl   = blockIdx.y;          // 0..8
    const int k = kl / 3, l = kl % 3;
    const int b    = tile >> 3;
    const int r0   = (tile & 7) * 4;

    const int mb = (wid >> 2) * 64;
    const int nb = (wid & 3) * 32;

    const uint32_t arow = (uint32_t)(ln & 15);
    const uint32_t acol = (uint32_t)((ln >> 4) * 8);
    const int brow = (ln & 7) + ((ln >> 4) & 1) * 8;
    const int bcol = ((ln >> 3) & 1) * 8;

    auto stage = [&](int h, int bu) {   // khalf h into buffer bu
        const uint32_t bufb = u0 + (uint32_t)bu * CHUNK_BYTES;
        const unsigned char* srcA_H = (const unsigned char*)g_featH;
        const unsigned char* srcA_L = (const unsigned char*)g_featL;
        const unsigned char* srcB_H = (const unsigned char*)g_Bh[kl];
        const unsigned char* srcB_L = (const unsigned char*)g_Bl[kl];
        #pragma unroll
        for (int rep = 0; rep < 4; rep++) {
            int ch = rep * 256 + tid;          // 0..1023
            int m = ch >> 3, j = ch & 7;
            uint32_t doff = (uint32_t)(m * (KP2 * 2) + j * 16);
            size_t abyte = (size_t)((b * HP + (r0 + (m >> 5) + k)) * WP + ((m & 31) + l)) * 256
                           + (size_t)h * 128 + (size_t)j * 16;
            CP_ASYNC16(bufb + doff,                srcA_H + abyte);
            CP_ASYNC16(bufb + HT_BYTES + doff,     srcA_L + abyte);
            size_t bbyte = (size_t)m * 256 + (size_t)h * 128 + (size_t)j * 16;
            CP_ASYNC16(bufb + 2 * HT_BYTES + doff, srcB_H + bbyte);
            CP_ASYNC16(bufb + 3 * HT_BYTES + doff, srcB_L + bbyte);
        }
        CP_COMMIT();
    };

    float c[4][4][4];
    #pragma unroll
    for (int mf = 0; mf < 4; mf++)
        #pragma unroll
        for (int nf = 0; nf < 4; nf++)
            #pragma unroll
            for (int q = 0; q < 4; q++) c[mf][nf][q] = 0.0f;

    stage(0, 0);
    stage(1, 1);

    #pragma unroll
    for (int q = 0; q < 2; q++) {
        if (q == 0) CP_WAIT1(); else CP_WAIT0();
        __syncthreads();

        const uint32_t uAh = u0 + (uint32_t)q * CHUNK_BYTES;
        const uint32_t uAl = uAh + HT_BYTES;
        const uint32_t uBh = uAh + 2 * HT_BYTES;
        const uint32_t uBl = uAh + 3 * HT_BYTES;

        #pragma unroll
        for (int ks = 0; ks < 4; ks++) {
            const uint32_t ka = (uint32_t)(ks * 32);
            uint32_t ah[4][4], al[4][4];
            #pragma unroll
            for (int mf = 0; mf < 4; mf++) {
                const uint32_t aoff = (uint32_t)((mb + mf * 16 + arow) * (KP2 * 2)) + acol * 2 + ka;
                LDSM_X4(ah[mf][0], ah[mf][1], ah[mf][2], ah[mf][3], uAh + aoff);
                LDSM_X4(al[mf][0], al[mf][1], al[mf][2], al[mf][3], uAl + aoff);
            }
            uint32_t bh[2][4], bl[2][4];
            #pragma unroll
            for (int g = 0; g < 2; g++) {
                const uint32_t boff = (uint32_t)(((nb + g * 16 + brow) * KP2 + bcol) * 2) + ka;
                LDSM_X4(bh[g][0], bh[g][1], bh[g][2], bh[g][3], uBh + boff);
                LDSM_X4(bl[g][0], bl[g][1], bl[g][2], bl[g][3], uBl + boff);
            }
            #pragma unroll
            for (int mf = 0; mf < 4; mf++) {
                #pragma unroll
                for (int nf = 0; nf < 4; nf++) {
                    const int g = nf >> 1, h2 = (nf & 1) * 2;
                    MMA16816(c[mf][nf], ah[mf][0], ah[mf][1], ah[mf][2], ah[mf][3], bh[g][h2], bh[g][h2 + 1]);
                    MMA16816(c[mf][nf], al[mf][0], al[mf][1], al[mf][2], al[mf][3], bh[g][h2], bh[g][h2 + 1]);
                    MMA16816(c[mf][nf], ah[mf][0], ah[mf][1], ah[mf][2], ah[mf][3], bl[g][h2], bl[g][h2 + 1]);
                }
            }
        }
    }

    float* dst = &g_part[kl][tile][0][0];
    const int row = ln >> 2;
    const int colb = (ln & 3) * 2;
    #pragma unroll
    for (int mf = 0; mf < 4; mf++) {
        #pragma unroll
        for (int nf = 0; nf < 4; nf++) {
            const int n0 = nb + nf * 8 + colb;
            const int m1 = mb + mf * 16 + row;
            *(float2*)&dst[m1 * 128 + n0]       = make_float2(c[mf][nf][0], c[mf][nf][1]);
            *(float2*)&dst[(m1 + 8) * 128 + n0] = make_float2(c[mf][nf][2], c[mf][nf][3]);
        }
    }
}

// ---------------- combine: sum 9 partials + atan2 ----------------
__global__ __launch_bounds__(256) void combine_kernel(float* __restrict__ out) {
    __shared__ float s_x[128][65];
    __shared__ float s_y[128][65];
    const int t = blockIdx.x;
    const int tid = threadIdx.x;

    for (int i = tid; i < 128 * 128; i += 256) {
        float v = 0.0f;
        #pragma unroll
        for (int g = 0; g < 9; g++) v += g_part[g][t][0][i];
        int m = i >> 7, n = i & 127;
        if (n < 64) s_x[m][n] = v;
        else        s_y[m][n - 64] = v;
    }
    __syncthreads();

    const int b = t >> 3;
    const int hbase = (t & 7) * 4;
    for (int i = tid; i < 64 * 128; i += 256) {
        int o = i >> 7, m = i & 127;
        float ang = atan2f(s_y[m][o], s_x[m][o]);
        int h = hbase + (m >> 5), w = m & 31;
        out[((b * COUT + o) * HH + h) * WW + w] = ang;
    }
}

// ---------------- launch ----------------
extern "C" void kernel_launch(void* const* d_in, const int* in_sizes, int n_in,
                              void* d_out, int out_size) {
    const float* x     = (const float*)d_in[0];
    const float* probe = (const float*)d_in[1];
    const float* outw  = (const float*)d_in[2];
    float* out = (float*)d_out;

    const int SMEM = 2 * CHUNK_BYTES;   // 147456 B
    cudaFuncSetAttribute(gemm_kernel, cudaFuncAttributeMaxDynamicSharedMemorySize, SMEM);

    prep_kernel<<<FEAT_BLOCKS + WGT_BLOCKS, 256>>>(x, probe, outw);
    {
        dim3 grid(NT, 9);
        gemm_kernel<<<grid, 256, SMEM>>>();
    }
    combine_kernel<<<NT, 256>>>(out);
    (void)in_sizes; (void)n_in; (void)out_size;
}